// round 4
// baseline (speedup 1.0000x reference)
#include <cuda_runtime.h>
#include <math_constants.h>

// Problem shape (fixed by reference setup_inputs)
constexpr int BS  = 128;
constexpr int SEQ = 4096;
constexpr int HID = 128;

constexpr int SPLIT = 16;                         // seq slices per batch
constexpr int ROWS  = SEQ / SPLIT;                // 256 rows per slice
constexpr int TOTAL_SLICES = BS * SPLIT;          // 2048
constexpr int WARPS   = 16;
constexpr int THREADS = WARPS * 32;               // 512
constexpr int RPW     = ROWS / WARPS;             // 16 rows per warp per slice
constexpr int MAX_OWN = 16;                       // max slices one CTA may own

// Scratch + barrier state (device globals: no allocation allowed)
__device__ float g_part_m[TOTAL_SLICES];
__device__ float g_part_l[TOTAL_SLICES];
__device__ float g_part_acc[TOTAL_SLICES * HID];
__device__ unsigned g_work      = 0;   // work-steal counter (reset by barrier releaser)
__device__ unsigned g_bar_count = 0;
__device__ unsigned g_bar_gen   = 0;   // monotone generation (sense-reversing)

// Persistent fused kernel. Phase 1: steal (batch, slice) work items, compute
// raw scores (kept in smem) + softmax partial (m, l, acc) -> global scratch.
// Grid barrier. Phase 2: read all partials for each owned slice's batch,
// normalize smem scores -> write attn probs; slice h==0 owner writes context.
__global__ __launch_bounds__(THREADS, 2)
void attn_fused(const float* __restrict__ dec,
                const float* __restrict__ enc,
                float* __restrict__ attn,          // [BS, SEQ]
                float* __restrict__ ctx)           // [BS, HID]
{
    __shared__ float s_scores[MAX_OWN][ROWS];     // 16 KB
    __shared__ int   s_ids[MAX_OWN];
    __shared__ float s_m[WARPS], s_l[WARPS];
    __shared__ float s_acc[WARPS][HID];           // 8 KB
    __shared__ int   s_cur;

    const int tid  = threadIdx.x;
    const int w    = tid >> 5;
    const int lane = tid & 31;

    int nown = 0;

    // ---------------- Phase 1: work-stealing score pass ----------------
    for (;;) {
        if (nown == MAX_OWN) break;               // capacity guard (pop-free)
        if (tid == 0) s_cur = (int)atomicAdd(&g_work, 1u);
        __syncthreads();                          // publish s_cur; also orders
                                                  // prev combine-reads vs s_m writes
        const int slice = s_cur;
        if (slice >= TOTAL_SLICES) break;

        const int b = slice >> 4;                 // SPLIT = 16
        const int h = slice & 15;

        const float4 d = *reinterpret_cast<const float4*>(dec + (size_t)b * HID + lane * 4);
        const float* eb = enc + ((size_t)b * SEQ + (size_t)h * ROWS) * HID;

        float m = -CUDART_INF_F;
        float l = 0.0f;
        float4 acc = make_float4(0.f, 0.f, 0.f, 0.f);

        const int r0 = w * RPW;
        #pragma unroll
        for (int r = r0; r < r0 + RPW; r += 4) {
            float4 e0 = *reinterpret_cast<const float4*>(eb + (size_t)(r + 0) * HID + lane * 4);
            float4 e1 = *reinterpret_cast<const float4*>(eb + (size_t)(r + 1) * HID + lane * 4);
            float4 e2 = *reinterpret_cast<const float4*>(eb + (size_t)(r + 2) * HID + lane * 4);
            float4 e3 = *reinterpret_cast<const float4*>(eb + (size_t)(r + 3) * HID + lane * 4);

            float sc0 = e0.x * d.x + e0.y * d.y + e0.z * d.z + e0.w * d.w;
            float sc1 = e1.x * d.x + e1.y * d.y + e1.z * d.z + e1.w * d.w;
            float sc2 = e2.x * d.x + e2.y * d.y + e2.z * d.z + e2.w * d.w;
            float sc3 = e3.x * d.x + e3.y * d.y + e3.z * d.z + e3.w * d.w;

            #pragma unroll
            for (int off = 16; off >= 1; off >>= 1) {
                sc0 += __shfl_xor_sync(0xFFFFFFFFu, sc0, off);
                sc1 += __shfl_xor_sync(0xFFFFFFFFu, sc1, off);
                sc2 += __shfl_xor_sync(0xFFFFFFFFu, sc2, off);
                sc3 += __shfl_xor_sync(0xFFFFFFFFu, sc3, off);
            }

            if (lane == 0) {
                s_scores[nown][r + 0] = sc0;
                s_scores[nown][r + 1] = sc1;
                s_scores[nown][r + 2] = sc2;
                s_scores[nown][r + 3] = sc3;
            }

            float mnew = fmaxf(fmaxf(fmaxf(sc0, sc1), fmaxf(sc2, sc3)), m);
            float scale = __expf(m - mnew);       // exp(-inf)=0 on first iter
            float p0 = __expf(sc0 - mnew);
            float p1 = __expf(sc1 - mnew);
            float p2 = __expf(sc2 - mnew);
            float p3 = __expf(sc3 - mnew);
            l = l * scale + (p0 + p1) + (p2 + p3);

            acc.x = acc.x * scale + p0 * e0.x + p1 * e1.x + p2 * e2.x + p3 * e3.x;
            acc.y = acc.y * scale + p0 * e0.y + p1 * e1.y + p2 * e2.y + p3 * e3.y;
            acc.z = acc.z * scale + p0 * e0.z + p1 * e1.z + p2 * e2.z + p3 * e3.z;
            acc.w = acc.w * scale + p0 * e0.w + p1 * e1.w + p2 * e2.w + p3 * e3.w;

            m = mnew;
        }

        if (lane == 0) { s_m[w] = m; s_l[w] = l; }
        *reinterpret_cast<float4*>(&s_acc[w][lane * 4]) = acc;
        __syncthreads();

        // combine warp partials -> slice partial (redundant per thread, cheap)
        float M = -CUDART_INF_F;
        #pragma unroll
        for (int i = 0; i < WARPS; ++i) M = fmaxf(M, s_m[i]);
        float L = 0.0f;
        #pragma unroll
        for (int i = 0; i < WARPS; ++i) L += s_l[i] * __expf(s_m[i] - M);

        if (tid == 0) {
            g_part_m[slice] = M;
            g_part_l[slice] = L;
            s_ids[nown] = slice;
        }
        if (tid < HID) {
            float c = 0.0f;
            #pragma unroll
            for (int i = 0; i < WARPS; ++i) c += s_acc[i][tid] * __expf(s_m[i] - M);
            g_part_acc[(size_t)slice * HID + tid] = c;  // unnormalized, at max M
        }
        ++nown;
    }

    // ---------------- Grid barrier (sense-reversing) ----------------
    __syncthreads();
    if (tid == 0) {
        __threadfence();                          // publish partials
        unsigned gen = atomicAdd(&g_bar_gen, 0u); // read generation BEFORE arriving
        unsigned old = atomicAdd(&g_bar_count, 1u);
        if (old == gridDim.x - 1) {
            atomicExch(&g_bar_count, 0u);
            atomicExch(&g_work, 0u);              // clean state for next graph replay
            __threadfence();
            atomicAdd(&g_bar_gen, 1u);            // release
        } else {
            while (atomicAdd(&g_bar_gen, 0u) == gen) __nanosleep(64);
        }
    }
    __syncthreads();

    // ---------------- Phase 2: normalize owned slices ----------------
    for (int i = 0; i < nown; ++i) {
        const int slice = s_ids[i];
        const int b = slice >> 4;
        const int h = slice & 15;

        float pm[SPLIT], pl[SPLIT];
        #pragma unroll
        for (int j = 0; j < SPLIT; ++j) {
            pm[j] = __ldcg(&g_part_m[b * SPLIT + j]);   // L2-only: skip stale L1
            pl[j] = __ldcg(&g_part_l[b * SPLIT + j]);
        }
        float M = pm[0];
        #pragma unroll
        for (int j = 1; j < SPLIT; ++j) M = fmaxf(M, pm[j]);
        float L = 0.0f;
        #pragma unroll
        for (int j = 0; j < SPLIT; ++j) L += pl[j] * __expf(pm[j] - M);
        const float invL = 1.0f / L;

        if (tid < ROWS) {
            attn[(size_t)b * SEQ + (size_t)h * ROWS + tid] =
                __expf(s_scores[i][tid] - M) * invL;
        }

        if (h == 0 && tid < HID) {
            float c = 0.0f;
            #pragma unroll
            for (int j = 0; j < SPLIT; ++j)
                c += __ldcg(&g_part_acc[(size_t)(b * SPLIT + j) * HID + tid])
                     * __expf(pm[j] - M);
            ctx[(size_t)b * HID + tid] = c * invL;
        }
    }
}

extern "C" void kernel_launch(void* const* d_in, const int* in_sizes, int n_in,
                              void* d_out, int out_size)
{
    const float* dec = (const float*)d_in[0];
    const float* enc = (const float*)d_in[1];
    if (n_in >= 2 && in_sizes[0] > in_sizes[1]) {
        dec = (const float*)d_in[1];
        enc = (const float*)d_in[0];
    }

    float* attn = (float*)d_out;                   // [BS, SEQ]
    float* ctx  = attn + (size_t)BS * SEQ;         // [BS, HID]

    // Grid must be fully co-resident for the software barrier.
    int dev = 0, sms = 148;
    cudaGetDevice(&dev);
    cudaDeviceGetAttribute(&sms, cudaDevAttrMultiProcessorCount, dev);
    int occ = 1;
    cudaOccupancyMaxActiveBlocksPerMultiprocessor(&occ, attn_fused, THREADS, 0);
    if (occ < 1) occ = 1;
    if (occ > 2) occ = 2;                          // lb caps at 2 anyway
    int grid = sms * occ;
    if (grid > TOTAL_SLICES) grid = TOTAL_SLICES;

    attn_fused<<<grid, THREADS>>>(dec, enc, attn, ctx);
}

// round 5
// speedup vs baseline: 1.4205x; 1.4205x over previous
#include <cuda_runtime.h>
#include <math_constants.h>

// Problem shape (fixed by reference setup_inputs)
constexpr int BS  = 128;
constexpr int SEQ = 4096;
constexpr int HID = 128;

constexpr int WARPS   = 32;
constexpr int THREADS = WARPS * 32;          // 1024
constexpr int ROWS_PER_WARP = SEQ / WARPS;   // 128

// One CTA per batch element, 32 warps for maximum memory-level parallelism.
// Flash-decode single pass over encoder rows:
//  - each warp owns a contiguous 128-row slice of seq
//  - per row: lane loads float4 of enc row (32 lanes * 4 = 128 = HID),
//    dot with dec (in registers), butterfly reduce -> score
//  - online softmax (m, l) + rescaled context accumulation using the SAME
//    enc float4 still in registers (enc touched exactly once from HBM)
//  - raw scores parked in smem; after the cross-warp combine the CTA
//    normalizes them from smem and writes attn_prob + context. No second
//    kernel, no global scratch, no atomics.
__global__ __launch_bounds__(THREADS, 1)
void seq2seq_attn_kernel(const float* __restrict__ dec,
                         const float* __restrict__ enc,
                         float* __restrict__ attn,   // [BS, SEQ]
                         float* __restrict__ ctx)    // [BS, HID]
{
    __shared__ float s_scores[SEQ];                 // 16 KB raw scores
    __shared__ float s_m[WARPS];
    __shared__ float s_l[WARPS];
    __shared__ float s_acc[WARPS][HID];             // 16 KB partial contexts

    const int b    = blockIdx.x;
    const int tid  = threadIdx.x;
    const int w    = tid >> 5;
    const int lane = tid & 31;

    // dec row: lane holds 4 contiguous components
    const float4 d = *reinterpret_cast<const float4*>(dec + (size_t)b * HID + lane * 4);

    const float* enc_b = enc + (size_t)b * SEQ * HID;

    float m = -CUDART_INF_F;
    float l = 0.0f;
    float4 acc = make_float4(0.f, 0.f, 0.f, 0.f);

    const int row0 = w * ROWS_PER_WARP;
    const int row1 = row0 + ROWS_PER_WARP;

    for (int r = row0; r < row1; r += 4) {
        float4 e0 = *reinterpret_cast<const float4*>(enc_b + (size_t)(r + 0) * HID + lane * 4);
        float4 e1 = *reinterpret_cast<const float4*>(enc_b + (size_t)(r + 1) * HID + lane * 4);
        float4 e2 = *reinterpret_cast<const float4*>(enc_b + (size_t)(r + 2) * HID + lane * 4);
        float4 e3 = *reinterpret_cast<const float4*>(enc_b + (size_t)(r + 3) * HID + lane * 4);

        float sc0 = e0.x * d.x + e0.y * d.y + e0.z * d.z + e0.w * d.w;
        float sc1 = e1.x * d.x + e1.y * d.y + e1.z * d.z + e1.w * d.w;
        float sc2 = e2.x * d.x + e2.y * d.y + e2.z * d.z + e2.w * d.w;
        float sc3 = e3.x * d.x + e3.y * d.y + e3.z * d.z + e3.w * d.w;

        // four independent butterfly reduces, interleaved for ILP
        #pragma unroll
        for (int off = 16; off >= 1; off >>= 1) {
            sc0 += __shfl_xor_sync(0xFFFFFFFFu, sc0, off);
            sc1 += __shfl_xor_sync(0xFFFFFFFFu, sc1, off);
            sc2 += __shfl_xor_sync(0xFFFFFFFFu, sc2, off);
            sc3 += __shfl_xor_sync(0xFFFFFFFFu, sc3, off);
        }

        if (lane == 0) {
            s_scores[r + 0] = sc0;
            s_scores[r + 1] = sc1;
            s_scores[r + 2] = sc2;
            s_scores[r + 3] = sc3;
        }

        float mnew = fmaxf(fmaxf(fmaxf(sc0, sc1), fmaxf(sc2, sc3)), m);
        float scale = __expf(m - mnew);           // exp(-inf)=0 on first iter
        float p0 = __expf(sc0 - mnew);
        float p1 = __expf(sc1 - mnew);
        float p2 = __expf(sc2 - mnew);
        float p3 = __expf(sc3 - mnew);
        l = l * scale + (p0 + p1) + (p2 + p3);

        acc.x = acc.x * scale + p0 * e0.x + p1 * e1.x + p2 * e2.x + p3 * e3.x;
        acc.y = acc.y * scale + p0 * e0.y + p1 * e1.y + p2 * e2.y + p3 * e3.y;
        acc.z = acc.z * scale + p0 * e0.z + p1 * e1.z + p2 * e2.z + p3 * e3.z;
        acc.w = acc.w * scale + p0 * e0.w + p1 * e1.w + p2 * e2.w + p3 * e3.w;

        m = mnew;
    }

    // per-warp results to smem
    if (lane == 0) { s_m[w] = m; s_l[w] = l; }
    *reinterpret_cast<float4*>(&s_acc[w][lane * 4]) = acc;
    __syncthreads();

    // every thread redundantly combines the 32 warp partials (cheap)
    float M = -CUDART_INF_F;
    #pragma unroll
    for (int i = 0; i < WARPS; ++i) M = fmaxf(M, s_m[i]);
    float L = 0.0f;
    #pragma unroll
    for (int i = 0; i < WARPS; ++i) L += s_l[i] * __expf(s_m[i] - M);
    const float invL = 1.0f / L;

    // context: threads 0..127 each own one hidden component
    // (s_acc[i][tid] strides 512B across i -> lanes 0..31 hit distinct banks)
    if (tid < HID) {
        float c = 0.0f;
        #pragma unroll
        for (int i = 0; i < WARPS; ++i) c += s_acc[i][tid] * __expf(s_m[i] - M);
        ctx[(size_t)b * HID + tid] = c * invL;
    }

    // attn_prob: normalize parked scores, one float4 per thread (coalesced)
    {
        float4 v = *reinterpret_cast<const float4*>(&s_scores[tid * 4]);
        v.x = __expf(v.x - M) * invL;
        v.y = __expf(v.y - M) * invL;
        v.z = __expf(v.z - M) * invL;
        v.w = __expf(v.w - M) * invL;
        *reinterpret_cast<float4*>(attn + (size_t)b * SEQ + tid * 4) = v;
    }
}

extern "C" void kernel_launch(void* const* d_in, const int* in_sizes, int n_in,
                              void* d_out, int out_size)
{
    const float* dec = (const float*)d_in[0];
    const float* enc = (const float*)d_in[1];
    if (n_in >= 2 && in_sizes[0] > in_sizes[1]) {
        dec = (const float*)d_in[1];
        enc = (const float*)d_in[0];
    }

    float* attn = (float*)d_out;                   // [BS, SEQ]
    float* ctx  = attn + (size_t)BS * SEQ;         // [BS, HID]

    seq2seq_attn_kernel<<<BS, THREADS>>>(dec, enc, attn, ctx);
}

// round 6
// speedup vs baseline: 1.4663x; 1.0322x over previous
#include <cuda_runtime.h>
#include <math_constants.h>

// Problem shape (fixed by reference setup_inputs)
constexpr int BS  = 128;
constexpr int SEQ = 4096;
constexpr int HID = 128;

constexpr int WARPS   = 32;
constexpr int THREADS = WARPS * 32;          // 1024
constexpr int ROWS_PER_WARP = SEQ / WARPS;   // 128

// One CTA per batch element, 32 warps. Lane remap: 16 lanes per row.
//   lane = sub*16 + i   (sub in {0,1} -> row parity, i in 0..15 -> hidden chunk)
// Each lane covers hidden positions {i*4..i*4+3} and {64+i*4..64+i*4+3}.
// Per 4-row group: lane handles rows rA=r+sub and rB=r+2+sub.
//   - 4 independent LDG.128 (each instruction: 2 rows x 256B contiguous)
//   - dot partials -> 4-level butterfly (xor 1,2,4,8) over 2 scores = 8 SHFL
//     (vs 20 SHFL for the 32-lane reduction)
//   - branch-guarded online softmax rescale (max updates ~5x per lane total)
//   - context partial accumulated with e-values still in registers
// Raw scores parked in smem; CTA-wide combine; probs + context written once.
__global__ __launch_bounds__(THREADS, 1)
void seq2seq_attn_kernel(const float* __restrict__ dec,
                         const float* __restrict__ enc,
                         float* __restrict__ attn,   // [BS, SEQ]
                         float* __restrict__ ctx)    // [BS, HID]
{
    __shared__ float s_scores[SEQ];                 // 16 KB raw scores
    __shared__ float s_m[WARPS];
    __shared__ float s_l[WARPS];
    __shared__ float s_acc[WARPS][HID];             // 16 KB partial contexts

    const int b    = blockIdx.x;
    const int tid  = threadIdx.x;
    const int w    = tid >> 5;
    const int lane = tid & 31;
    const int sub  = lane >> 4;                     // 0 or 1
    const int i    = lane & 15;                     // hidden chunk index

    // dec chunks for this lane: floats [i*4..i*4+3] and [64+i*4..64+i*4+3]
    const float* dec_b = dec + (size_t)b * HID;
    const float4 d0 = *reinterpret_cast<const float4*>(dec_b + i * 4);
    const float4 d1 = *reinterpret_cast<const float4*>(dec_b + 64 + i * 4);

    const float* enc_b = enc + (size_t)b * SEQ * HID;

    float m = -CUDART_INF_F;
    float l = 0.0f;
    float4 acc0 = make_float4(0.f, 0.f, 0.f, 0.f);  // hidden chunk k=0
    float4 acc1 = make_float4(0.f, 0.f, 0.f, 0.f);  // hidden chunk k=1

    const int row0 = w * ROWS_PER_WARP;
    const int row1 = row0 + ROWS_PER_WARP;

    for (int r = row0; r < row1; r += 4) {
        const int rowA = r + sub;
        const int rowB = r + 2 + sub;
        const float* pA = enc_b + (size_t)rowA * HID;
        const float* pB = enc_b + (size_t)rowB * HID;

        // 4 independent vector loads (MLP=4)
        float4 e00 = *reinterpret_cast<const float4*>(pA + i * 4);
        float4 e01 = *reinterpret_cast<const float4*>(pA + 64 + i * 4);
        float4 e10 = *reinterpret_cast<const float4*>(pB + i * 4);
        float4 e11 = *reinterpret_cast<const float4*>(pB + 64 + i * 4);

        float scA = e00.x * d0.x + e00.y * d0.y + e00.z * d0.z + e00.w * d0.w
                  + e01.x * d1.x + e01.y * d1.y + e01.z * d1.z + e01.w * d1.w;
        float scB = e10.x * d0.x + e10.y * d0.y + e10.z * d0.z + e10.w * d0.w
                  + e11.x * d1.x + e11.y * d1.y + e11.z * d1.z + e11.w * d1.w;

        // 4-level butterfly within the 16-lane row group, 2 scores interleaved
        #pragma unroll
        for (int off = 8; off >= 1; off >>= 1) {
            scA += __shfl_xor_sync(0xFFFFFFFFu, scA, off);
            scB += __shfl_xor_sync(0xFFFFFFFFu, scB, off);
        }

        if (i == 0) {                               // 2 lanes store 2 scores
            s_scores[rowA] = scA;
            s_scores[rowB] = scB;
        }

        // row A: branch-guarded online softmax + context accumulation
        if (scA > m) {
            float cs = __expf(m - scA);             // exp(-inf)=0 first time
            m = scA;
            l *= cs;
            acc0.x *= cs; acc0.y *= cs; acc0.z *= cs; acc0.w *= cs;
            acc1.x *= cs; acc1.y *= cs; acc1.z *= cs; acc1.w *= cs;
        }
        float pAe = __expf(scA - m);
        l += pAe;
        acc0.x += pAe * e00.x; acc0.y += pAe * e00.y;
        acc0.z += pAe * e00.z; acc0.w += pAe * e00.w;
        acc1.x += pAe * e01.x; acc1.y += pAe * e01.y;
        acc1.z += pAe * e01.z; acc1.w += pAe * e01.w;

        // row B
        if (scB > m) {
            float cs = __expf(m - scB);
            m = scB;
            l *= cs;
            acc0.x *= cs; acc0.y *= cs; acc0.z *= cs; acc0.w *= cs;
            acc1.x *= cs; acc1.y *= cs; acc1.z *= cs; acc1.w *= cs;
        }
        float pBe = __expf(scB - m);
        l += pBe;
        acc0.x += pBe * e10.x; acc0.y += pBe * e10.y;
        acc0.z += pBe * e10.z; acc0.w += pBe * e10.w;
        acc1.x += pBe * e11.x; acc1.y += pBe * e11.y;
        acc1.z += pBe * e11.z; acc1.w += pBe * e11.w;
    }

    // ---- cross-sub combine (one butterfly level, once per warp) ----
    float m_o = __shfl_xor_sync(0xFFFFFFFFu, m, 16);
    float l_o = __shfl_xor_sync(0xFFFFFFFFu, l, 16);
    float Mw = fmaxf(m, m_o);
    float sSelf  = __expf(m - Mw);
    float sOther = __expf(m_o - Mw);
    float Lw = l * sSelf + l_o * sOther;

    float4 a0o, a1o;
    a0o.x = __shfl_xor_sync(0xFFFFFFFFu, acc0.x, 16);
    a0o.y = __shfl_xor_sync(0xFFFFFFFFu, acc0.y, 16);
    a0o.z = __shfl_xor_sync(0xFFFFFFFFu, acc0.z, 16);
    a0o.w = __shfl_xor_sync(0xFFFFFFFFu, acc0.w, 16);
    a1o.x = __shfl_xor_sync(0xFFFFFFFFu, acc1.x, 16);
    a1o.y = __shfl_xor_sync(0xFFFFFFFFu, acc1.y, 16);
    a1o.z = __shfl_xor_sync(0xFFFFFFFFu, acc1.z, 16);
    a1o.w = __shfl_xor_sync(0xFFFFFFFFu, acc1.w, 16);

    if (sub == 0) {                                 // lanes 0..15 hold the warp total
        float4 t0, t1;
        t0.x = acc0.x * sSelf + a0o.x * sOther;
        t0.y = acc0.y * sSelf + a0o.y * sOther;
        t0.z = acc0.z * sSelf + a0o.z * sOther;
        t0.w = acc0.w * sSelf + a0o.w * sOther;
        t1.x = acc1.x * sSelf + a1o.x * sOther;
        t1.y = acc1.y * sSelf + a1o.y * sOther;
        t1.z = acc1.z * sSelf + a1o.z * sOther;
        t1.w = acc1.w * sSelf + a1o.w * sOther;
        *reinterpret_cast<float4*>(&s_acc[w][i * 4])      = t0;
        *reinterpret_cast<float4*>(&s_acc[w][64 + i * 4]) = t1;
    }
    if (lane == 0) { s_m[w] = Mw; s_l[w] = Lw; }
    __syncthreads();

    // ---- CTA combine: every thread redundantly folds 32 warp partials ----
    float M = -CUDART_INF_F;
    #pragma unroll
    for (int j = 0; j < WARPS; ++j) M = fmaxf(M, s_m[j]);
    float L = 0.0f;
    #pragma unroll
    for (int j = 0; j < WARPS; ++j) L += s_l[j] * __expf(s_m[j] - M);
    const float invL = 1.0f / L;

    // context: threads 0..127 each own one hidden component
    if (tid < HID) {
        float c = 0.0f;
        #pragma unroll
        for (int j = 0; j < WARPS; ++j) c += s_acc[j][tid] * __expf(s_m[j] - M);
        ctx[(size_t)b * HID + tid] = c * invL;
    }

    // attn_prob: normalize parked scores, one float4 per thread (coalesced)
    {
        float4 v = *reinterpret_cast<const float4*>(&s_scores[tid * 4]);
        v.x = __expf(v.x - M) * invL;
        v.y = __expf(v.y - M) * invL;
        v.z = __expf(v.z - M) * invL;
        v.w = __expf(v.w - M) * invL;
        *reinterpret_cast<float4*>(attn + (size_t)b * SEQ + tid * 4) = v;
    }
}

extern "C" void kernel_launch(void* const* d_in, const int* in_sizes, int n_in,
                              void* d_out, int out_size)
{
    const float* dec = (const float*)d_in[0];
    const float* enc = (const float*)d_in[1];
    if (n_in >= 2 && in_sizes[0] > in_sizes[1]) {
        dec = (const float*)d_in[1];
        enc = (const float*)d_in[0];
    }

    float* attn = (float*)d_out;                   // [BS, SEQ]
    float* ctx  = attn + (size_t)BS * SEQ;         // [BS, HID]

    seq2seq_attn_kernel<<<BS, THREADS>>>(dec, enc, attn, ctx);
}